// round 1
// baseline (speedup 1.0000x reference)
#include <cuda_runtime.h>
#include <math.h>

// ---------------- problem constants ----------------
#define BB   4
#define TT   827
#define CC   256
#define HH   8
#define DHH  32
#define LL   12
#define FF   1024            // 4*C
#define MM   (BB*TT)         // 3308 rows
#define VOC  16384

// ---------------- scratch (device globals; no allocs allowed) ----------------
__device__ float g_x  [MM*CC];
__device__ float g_xn [MM*CC];
__device__ float g_q  [MM*CC];
__device__ float g_k  [MM*CC];
__device__ float g_v  [MM*CC];
__device__ float g_y  [MM*CC];
__device__ float g_ffn[MM*FF];
__device__ float g_h  [(long)BB*TT*TT];   // additive attention bias (even layers)
__device__ float g_z1 [3*BB*60];

__device__ __forceinline__ float gelu_exact(float z) {
    return 0.5f * z * (1.0f + erff(z * 0.70710678118654752f));
}

// ---------------- locality MLP stage 1: z1 = gelu(p @ W1^T + b1) ----------------
__global__ void loc1_kernel(const float* __restrict__ p1, const float* __restrict__ p2,
                            const float* __restrict__ p3, const float* __restrict__ W1,
                            const float* __restrict__ b1) {
    int mat = blockIdx.x / BB;
    int b   = blockIdx.x % BB;
    int j   = threadIdx.x;
    if (j >= 60) return;
    const float* p = (mat == 0) ? p1 : (mat == 1) ? p2 : p3;
    float s = b1[j];
    #pragma unroll
    for (int i = 0; i < 30; i++) s += p[b*30 + i] * W1[j*30 + i];
    g_z1[(mat*BB + b)*60 + j] = gelu_exact(s);
}

// ---------------- zero h ----------------
__global__ void zero_h_kernel() {
    long i = (long)blockIdx.x * blockDim.x + threadIdx.x;
    if (i < (long)BB*TT*TT) g_h[i] = 0.0f;
}

// ---------------- locality MLP stage 2: fill h blocks ----------------
__global__ void loc2_kernel(const float* __restrict__ W2, const float* __restrict__ b2) {
    int idx = blockIdx.x * blockDim.x + threadIdx.x;
    const int total = 3 * BB * 65536;
    if (idx >= total) return;
    int mat = idx / (BB * 65536);
    int rem = idx % (BB * 65536);
    int b   = rem / 65536;
    int o   = rem % 65536;
    const float* z1 = &g_z1[(mat*BB + b)*60];
    const float* wr = &W2[(long)o * 60];
    float s = b2[o];
    #pragma unroll
    for (int j = 0; j < 60; j++) s += z1[j] * wr[j];
    int r = o >> 8, c = o & 255;
    int r0 = (mat == 0) ? 285 : 571;
    int c0 = (mat == 2) ? 286 : 0;
    g_h[((long)b*TT + (r0 + r))*TT + (c0 + c)] = s;
}

// ---------------- embedding: x = tok + role + time ----------------
__global__ void embed_kernel(const float* __restrict__ dc, const float* __restrict__ z,
                             const float* __restrict__ frame, const float* __restrict__ cam,
                             const float* __restrict__ timee) {
    int idx = blockIdx.x * blockDim.x + threadIdx.x;
    if (idx >= MM*CC) return;
    int c = idx % CC;
    int t = (idx / CC) % TT;
    int b = idx / (CC * TT);
    float tok = (t < 572) ? dc[((long)b*572 + t)*CC + c]
                          : z [((long)b*256 + (t - 572))*CC + c];
    float role;
    if      (t < 256) role = frame[(t      )*CC + c];
    else if (t < 286) role = cam  [(t - 256)*CC + c];
    else if (t < 542) role = frame[(t - 286)*CC + c];
    else if (t < 572) role = cam  [(t - 542)*CC + c];
    else              role = frame[(t - 572)*CC + c];
    g_x[idx] = tok + role + timee[t*CC + c];
}

// ---------------- layernorm (one block per row, 256 threads) ----------------
__global__ void ln_kernel(const float* __restrict__ x, const float* __restrict__ w,
                          const float* __restrict__ b, float* __restrict__ out) {
    int row = blockIdx.x;
    int tid = threadIdx.x;
    __shared__ float s[CC];
    float v = x[(long)row*CC + tid];
    s[tid] = v; __syncthreads();
    for (int st = 128; st > 0; st >>= 1) { if (tid < st) s[tid] += s[tid + st]; __syncthreads(); }
    float mean = s[0] * (1.0f / CC); __syncthreads();
    float d = v - mean;
    s[tid] = d * d; __syncthreads();
    for (int st = 128; st > 0; st >>= 1) { if (tid < st) s[tid] += s[tid + st]; __syncthreads(); }
    float var = s[0] * (1.0f / CC);
    out[(long)row*CC + tid] = d * rsqrtf(var + 1e-5f) * w[tid] + b[tid];
}

// ---------------- tiled fp32 GEMM: out = act(A @ W^T + bias) (+ res) ----------------
// A: (M,K) row-major; W: (N,K) row-major; out: (M,N)
template<bool DO_GELU, bool DO_RES>
__global__ void gemm_kernel(const float* __restrict__ A, const float* __restrict__ W,
                            const float* __restrict__ bias, const float* __restrict__ res,
                            float* __restrict__ out, int M, int N, int K) {
    constexpr int BM = 64, BN = 64, BK = 16;
    __shared__ float As[BM][BK];
    __shared__ float Bs[BN][BK];
    int tid = threadIdx.x;
    int tm = (tid >> 4) << 2;          // 0..60 step 4
    int tn = (tid & 15) << 2;          // 0..60 step 4
    int m0 = blockIdx.y * BM;
    int n0 = blockIdx.x * BN;
    float acc[4][4] = {};
    for (int k0 = 0; k0 < K; k0 += BK) {
        #pragma unroll
        for (int i = tid; i < BM*BK; i += 256) {
            int r = i >> 4, c = i & 15;
            int m = m0 + r;
            As[r][c] = (m < M) ? A[(long)m*K + k0 + c] : 0.0f;
            Bs[r][c] = W[(long)(n0 + r)*K + k0 + c];
        }
        __syncthreads();
        #pragma unroll
        for (int kk = 0; kk < BK; kk++) {
            float a0 = As[tm+0][kk], a1 = As[tm+1][kk], a2 = As[tm+2][kk], a3 = As[tm+3][kk];
            float b0 = Bs[tn+0][kk], b1 = Bs[tn+1][kk], b2 = Bs[tn+2][kk], b3 = Bs[tn+3][kk];
            acc[0][0] += a0*b0; acc[0][1] += a0*b1; acc[0][2] += a0*b2; acc[0][3] += a0*b3;
            acc[1][0] += a1*b0; acc[1][1] += a1*b1; acc[1][2] += a1*b2; acc[1][3] += a1*b3;
            acc[2][0] += a2*b0; acc[2][1] += a2*b1; acc[2][2] += a2*b2; acc[2][3] += a2*b3;
            acc[3][0] += a3*b0; acc[3][1] += a3*b1; acc[3][2] += a3*b2; acc[3][3] += a3*b3;
        }
        __syncthreads();
    }
    #pragma unroll
    for (int i = 0; i < 4; i++) {
        int m = m0 + tm + i;
        if (m >= M) continue;
        #pragma unroll
        for (int j = 0; j < 4; j++) {
            int n = n0 + tn + j;
            float v = acc[i][j];
            if (bias) v += bias[n];
            if (DO_GELU) v = gelu_exact(v);
            if (DO_RES)  v += res[(long)m*N + n];
            out[(long)m*N + n] = v;
        }
    }
}

// ---------------- attention: one block per (b,h,q), 128 threads ----------------
__global__ void attn_kernel(int adaptive) {
    int qt = blockIdx.x;
    int bh = blockIdx.y;
    int b = bh >> 3, h = bh & 7;
    int tid = threadIdx.x;
    __shared__ float sq[DHH];
    __shared__ float sc[TT + 5];
    __shared__ float red[128];
    __shared__ float red2[4][DHH];
    const float scale = 0.1767766952966369f;  // 1/sqrt(32)

    if (tid < DHH) sq[tid] = g_q[((long)(b*TT + qt))*CC + h*DHH + tid];
    __syncthreads();

    int nk = qt + 1;
    float lmax = -1e30f;
    for (int kt = tid; kt < nk; kt += 128) {
        const float* kr = &g_k[((long)(b*TT + kt))*CC + h*DHH];
        float s = 0.0f;
        #pragma unroll
        for (int d = 0; d < DHH; d++) s += sq[d] * kr[d];
        s *= scale;
        if (adaptive) s += g_h[((long)b*TT + qt)*TT + kt];
        sc[kt] = s;
        lmax = fmaxf(lmax, s);
    }
    red[tid] = lmax; __syncthreads();
    for (int st = 64; st > 0; st >>= 1) { if (tid < st) red[tid] = fmaxf(red[tid], red[tid + st]); __syncthreads(); }
    float m = red[0]; __syncthreads();

    float lsum = 0.0f;
    for (int kt = tid; kt < nk; kt += 128) {
        float p = expf(sc[kt] - m);
        sc[kt] = p;
        lsum += p;
    }
    red[tid] = lsum; __syncthreads();
    for (int st = 64; st > 0; st >>= 1) { if (tid < st) red[tid] += red[tid + st]; __syncthreads(); }
    float inv = 1.0f / red[0];
    __syncthreads();

    int d = tid & 31, g = tid >> 5;
    float acc = 0.0f;
    for (int kt = g; kt < nk; kt += 4) {
        acc += sc[kt] * g_v[((long)(b*TT + kt))*CC + h*DHH + d];
    }
    red2[g][d] = acc; __syncthreads();
    if (g == 0) {
        float yv = (red2[0][d] + red2[1][d] + red2[2][d] + red2[3][d]) * inv;
        g_y[((long)(b*TT + qt))*CC + h*DHH + d] = yv;
    }
}

// ---------------- launch ----------------
extern "C" void kernel_launch(void* const* d_in, const int* in_sizes, int n_in,
                              void* d_out, int out_size) {
    const float* dc      = (const float*)d_in[0];
    const float* z       = (const float*)d_in[1];
    const float* p1      = (const float*)d_in[2];
    const float* p2      = (const float*)d_in[3];
    const float* p3      = (const float*)d_in[4];
    const float* frame   = (const float*)d_in[5];
    const float* cam     = (const float*)d_in[6];
    const float* timee   = (const float*)d_in[7];
    const float* locW1   = (const float*)d_in[8];
    const float* locb1   = (const float*)d_in[9];
    const float* locW2   = (const float*)d_in[10];
    const float* locb2   = (const float*)d_in[11];
    const float* ln1w    = (const float*)d_in[12];
    const float* ln1b    = (const float*)d_in[13];
    const float* Wq      = (const float*)d_in[14];
    const float* bq      = (const float*)d_in[15];
    const float* Wk      = (const float*)d_in[16];
    const float* bk      = (const float*)d_in[17];
    const float* Wv      = (const float*)d_in[18];
    const float* bv      = (const float*)d_in[19];
    const float* Wo      = (const float*)d_in[20];
    const float* bo      = (const float*)d_in[21];
    const float* ln2w    = (const float*)d_in[22];
    const float* ln2b    = (const float*)d_in[23];
    const float* W1      = (const float*)d_in[24];
    const float* b1      = (const float*)d_in[25];
    const float* W2      = (const float*)d_in[26];
    const float* b2      = (const float*)d_in[27];
    const float* lnfw    = (const float*)d_in[28];
    const float* lnfb    = (const float*)d_in[29];
    const float* headW   = (const float*)d_in[30];

    float *xp, *xnp, *qp, *kp, *vp, *yp, *ffnp;
    cudaGetSymbolAddress((void**)&xp,   g_x);
    cudaGetSymbolAddress((void**)&xnp,  g_xn);
    cudaGetSymbolAddress((void**)&qp,   g_q);
    cudaGetSymbolAddress((void**)&kp,   g_k);
    cudaGetSymbolAddress((void**)&vp,   g_v);
    cudaGetSymbolAddress((void**)&yp,   g_y);
    cudaGetSymbolAddress((void**)&ffnp, g_ffn);

    // attention bias h (built once per call)
    {
        long nh = (long)BB*TT*TT;
        zero_h_kernel<<<(int)((nh + 255) / 256), 256>>>();
        loc1_kernel<<<3*BB, 64>>>(p1, p2, p3, locW1, locb1);
        loc2_kernel<<<(3*BB*65536 + 127) / 128, 128>>>(locW2, locb2);
    }

    embed_kernel<<<(MM*CC + 255) / 256, 256>>>(dc, z, frame, cam, timee);

    dim3 gemm_cc(CC/64, (MM + 63) / 64);
    dim3 gemm_ff(FF/64, (MM + 63) / 64);
    dim3 attn_grid(TT, BB*HH);

    for (int l = 0; l < LL; l++) {
        ln_kernel<<<MM, CC>>>(xp, ln1w + l*CC, ln1b + l*CC, xnp);

        gemm_kernel<false,false><<<gemm_cc, 256>>>(xnp, Wq + (long)l*CC*CC, bq + l*CC, nullptr, qp, MM, CC, CC);
        gemm_kernel<false,false><<<gemm_cc, 256>>>(xnp, Wk + (long)l*CC*CC, bk + l*CC, nullptr, kp, MM, CC, CC);
        gemm_kernel<false,false><<<gemm_cc, 256>>>(xnp, Wv + (long)l*CC*CC, bv + l*CC, nullptr, vp, MM, CC, CC);

        attn_kernel<<<attn_grid, 128>>>((l % 2 == 0) ? 1 : 0);

        gemm_kernel<false,true><<<gemm_cc, 256>>>(yp, Wo + (long)l*CC*CC, bo + l*CC, xp, xp, MM, CC, CC);

        ln_kernel<<<MM, CC>>>(xp, ln2w + l*CC, ln2b + l*CC, xnp);

        gemm_kernel<true,false><<<gemm_ff, 256>>>(xnp, W1 + (long)l*FF*CC, b1 + (long)l*FF, nullptr, ffnp, MM, FF, CC);
        gemm_kernel<false,true><<<gemm_cc, 256>>>(ffnp, W2 + (long)l*CC*FF, b2 + l*CC, xp, xp, MM, CC, FF);
    }

    ln_kernel<<<MM, CC>>>(xp, lnfw, lnfb, xnp);

    dim3 gemm_head(VOC/64, (MM + 63) / 64);
    gemm_kernel<false,false><<<gemm_head, 256>>>(xnp, headW, nullptr, nullptr, (float*)d_out, MM, VOC, CC);
}

// round 3
// speedup vs baseline: 4.4233x; 4.4233x over previous
#include <cuda_runtime.h>
#include <math.h>

// ---------------- problem constants ----------------
#define BB   4
#define TT   827
#define CC   256
#define HH   8
#define DHH  32
#define LL   12
#define FF   1024            // 4*C
#define MM   (BB*TT)         // 3308 rows
#define VOC  16384
#define QKVN 768

// ---------------- scratch (device globals; no allocs allowed) ----------------
__device__ float g_x   [MM*CC];
__device__ float g_xn  [MM*CC];
__device__ float g_qkv [MM*QKVN];
__device__ float g_y   [MM*CC];
__device__ float g_ffn [MM*FF];
__device__ float g_h   [(long)BB*TT*TT];   // additive attention bias (even layers)
__device__ float g_z1  [3*BB*60];
__device__ float g_wqkv[(long)LL*QKVN*CC]; // packed [l][n(768)][k(256)]
__device__ float g_bqkv[LL*QKVN];

__device__ __forceinline__ float gelu_exact(float z) {
    return 0.5f * z * (1.0f + erff(z * 0.70710678118654752f));
}

__device__ __forceinline__ unsigned f2tf32(float x) {
    unsigned r;
    asm("cvt.rna.tf32.f32 %0, %1;" : "=r"(r) : "f"(x));
    return r;
}

// ---------------- weight packing for fused QKV ----------------
__global__ void pack_qkv_w(const float* __restrict__ Wq, const float* __restrict__ Wk,
                           const float* __restrict__ Wv) {
    long idx = (long)blockIdx.x * blockDim.x + threadIdx.x;
    if (idx >= (long)LL*QKVN*CC) return;
    int k = (int)(idx % CC);
    int n = (int)((idx / CC) % QKVN);
    int l = (int)(idx / ((long)CC*QKVN));
    const float* src;
    if      (n < 256) src = &Wq[((long)l*256 + n      )*CC];
    else if (n < 512) src = &Wk[((long)l*256 + n - 256)*CC];
    else              src = &Wv[((long)l*256 + n - 512)*CC];
    g_wqkv[idx] = src[k];
}

__global__ void pack_qkv_b(const float* __restrict__ bq, const float* __restrict__ bk,
                           const float* __restrict__ bv) {
    int idx = blockIdx.x * blockDim.x + threadIdx.x;
    if (idx >= LL*QKVN) return;
    int n = idx % QKVN;
    int l = idx / QKVN;
    float v;
    if      (n < 256) v = bq[l*256 + n];
    else if (n < 512) v = bk[l*256 + n - 256];
    else              v = bv[l*256 + n - 512];
    g_bqkv[idx] = v;
}

// ---------------- locality MLP stage 1 ----------------
__global__ void loc1_kernel(const float* __restrict__ p1, const float* __restrict__ p2,
                            const float* __restrict__ p3, const float* __restrict__ W1,
                            const float* __restrict__ b1) {
    int mat = blockIdx.x / BB;
    int b   = blockIdx.x % BB;
    int j   = threadIdx.x;
    if (j >= 60) return;
    const float* p = (mat == 0) ? p1 : (mat == 1) ? p2 : p3;
    float s = b1[j];
    #pragma unroll
    for (int i = 0; i < 30; i++) s += p[b*30 + i] * W1[j*30 + i];
    g_z1[(mat*BB + b)*60 + j] = gelu_exact(s);
}

__global__ void zero_h_kernel() {
    long i = (long)blockIdx.x * blockDim.x + threadIdx.x;
    if (i < (long)BB*TT*TT) g_h[i] = 0.0f;
}

__global__ void loc2_kernel(const float* __restrict__ W2, const float* __restrict__ b2) {
    int idx = blockIdx.x * blockDim.x + threadIdx.x;
    const int total = 3 * BB * 65536;
    if (idx >= total) return;
    int mat = idx / (BB * 65536);
    int rem = idx % (BB * 65536);
    int b   = rem / 65536;
    int o   = rem % 65536;
    const float* z1 = &g_z1[(mat*BB + b)*60];
    const float* wr = &W2[(long)o * 60];
    float s = b2[o];
    #pragma unroll
    for (int j = 0; j < 60; j++) s += z1[j] * wr[j];
    int r = o >> 8, c = o & 255;
    int r0 = (mat == 0) ? 285 : 571;
    int c0 = (mat == 2) ? 286 : 0;
    g_h[((long)b*TT + (r0 + r))*TT + (c0 + c)] = s;
}

// ---------------- embedding ----------------
__global__ void embed_kernel(const float* __restrict__ dc, const float* __restrict__ z,
                             const float* __restrict__ frame, const float* __restrict__ cam,
                             const float* __restrict__ timee) {
    int idx = blockIdx.x * blockDim.x + threadIdx.x;
    if (idx >= MM*CC) return;
    int c = idx % CC;
    int t = (idx / CC) % TT;
    int b = idx / (CC * TT);
    float tok = (t < 572) ? dc[((long)b*572 + t)*CC + c]
                          : z [((long)b*256 + (t - 572))*CC + c];
    float role;
    if      (t < 256) role = frame[(t      )*CC + c];
    else if (t < 286) role = cam  [(t - 256)*CC + c];
    else if (t < 542) role = frame[(t - 286)*CC + c];
    else if (t < 572) role = cam  [(t - 542)*CC + c];
    else              role = frame[(t - 572)*CC + c];
    g_x[idx] = tok + role + timee[t*CC + c];
}

// ---------------- layernorm ----------------
__global__ void ln_kernel(const float* __restrict__ x, const float* __restrict__ w,
                          const float* __restrict__ b, float* __restrict__ out) {
    int row = blockIdx.x;
    int tid = threadIdx.x;
    __shared__ float s[CC];
    float v = x[(long)row*CC + tid];
    s[tid] = v; __syncthreads();
    for (int st = 128; st > 0; st >>= 1) { if (tid < st) s[tid] += s[tid + st]; __syncthreads(); }
    float mean = s[0] * (1.0f / CC); __syncthreads();
    float d = v - mean;
    s[tid] = d * d; __syncthreads();
    for (int st = 128; st > 0; st >>= 1) { if (tid < st) s[tid] += s[tid + st]; __syncthreads(); }
    float var = s[0] * (1.0f / CC);
    out[(long)row*CC + tid] = d * rsqrtf(var + 1e-5f) * w[tid] + b[tid];
}

// ---------------- tensor-core TF32 GEMM: out = act(A @ W^T + bias) (+res) ----------------
// A: (M,K) row-major lda; W: (N,K) row-major; out: (M,ldo)
// Tile 128x64x16, 256 threads = 8 warps (4 m x 2 n), warp does 32x32 via m16n8k8.
#define SM_STRIDE 20   // floats; 16B-aligned rows AND conflict-free fragment reads

__device__ __forceinline__ void cp_async16(unsigned dst, const void* src, int bytes) {
    asm volatile("cp.async.ca.shared.global [%0], [%1], 16, %2;\n"
                 :: "r"(dst), "l"(src), "r"(bytes));
}

template<bool DO_GELU, bool DO_RES>
__global__ void __launch_bounds__(256)
gemm_tc(const float* __restrict__ A, int lda,
        const float* __restrict__ W,
        const float* __restrict__ bias,
        const float* __restrict__ res,
        float* __restrict__ out, int ldo,
        int M, int N, int K) {
    __shared__ float As[2][128*SM_STRIDE];
    __shared__ float Bs[2][64*SM_STRIDE];

    const int tid  = threadIdx.x;
    const int m0   = blockIdx.y * 128;
    const int n0   = blockIdx.x * 64;
    const int warp = tid >> 5, lane = tid & 31;
    const int wm = warp >> 1, wn = warp & 1;
    const int grp = lane >> 2, qd = lane & 3;

    float c[2][4][4];
    #pragma unroll
    for (int i = 0; i < 2; i++)
        #pragma unroll
        for (int j = 0; j < 4; j++)
            #pragma unroll
            for (int k = 0; k < 4; k++) c[i][j][k] = 0.0f;

    // precomputed staging coordinates
    const int a_r0 = tid >> 2,         a_c0 = (tid & 3) << 2;           // chunk tid
    const int a_r1 = (tid + 256) >> 2, a_c1 = (tid & 3) << 2;           // chunk tid+256
    const int b_r  = tid >> 2,         b_c  = (tid & 3) << 2;

    unsigned sA[2], sB[2];
    sA[0] = (unsigned)__cvta_generic_to_shared(&As[0][0]);
    sA[1] = (unsigned)__cvta_generic_to_shared(&As[1][0]);
    sB[0] = (unsigned)__cvta_generic_to_shared(&Bs[0][0]);
    sB[1] = (unsigned)__cvta_generic_to_shared(&Bs[1][0]);

    auto load_tiles = [&](int k0, int buf) {
        int m = m0 + a_r0;
        const float* src = A + (long)(m < M ? m : 0) * lda + k0 + a_c0;
        cp_async16(sA[buf] + (a_r0*SM_STRIDE + a_c0)*4, src, m < M ? 16 : 0);
        m = m0 + a_r1;
        src = A + (long)(m < M ? m : 0) * lda + k0 + a_c1;
        cp_async16(sA[buf] + (a_r1*SM_STRIDE + a_c1)*4, src, m < M ? 16 : 0);
        const float* srcb = W + (long)(n0 + b_r) * K + k0 + b_c;
        cp_async16(sB[buf] + (b_r*SM_STRIDE + b_c)*4, srcb, 16);
        asm volatile("cp.async.commit_group;\n");
    };

    auto compute = [&](int buf) {
        const float* pa = As[buf];
        const float* pb = Bs[buf];
        #pragma unroll
        for (int ks = 0; ks < 2; ks++) {
            const int kk = ks * 8;
            unsigned a[2][4], b[4][2];
            #pragma unroll
            for (int mi = 0; mi < 2; mi++) {
                int r = wm*32 + mi*16 + grp;
                a[mi][0] = f2tf32(pa[(r    )*SM_STRIDE + kk + qd    ]);
                a[mi][1] = f2tf32(pa[(r + 8)*SM_STRIDE + kk + qd    ]);
                a[mi][2] = f2tf32(pa[(r    )*SM_STRIDE + kk + qd + 4]);
                a[mi][3] = f2tf32(pa[(r + 8)*SM_STRIDE + kk + qd + 4]);
            }
            #pragma unroll
            for (int ni = 0; ni < 4; ni++) {
                int n = wn*32 + ni*8 + grp;
                b[ni][0] = f2tf32(pb[n*SM_STRIDE + kk + qd    ]);
                b[ni][1] = f2tf32(pb[n*SM_STRIDE + kk + qd + 4]);
            }
            #pragma unroll
            for (int mi = 0; mi < 2; mi++)
                #pragma unroll
                for (int ni = 0; ni < 4; ni++) {
                    asm volatile(
                        "mma.sync.aligned.m16n8k8.row.col.f32.tf32.tf32.f32 "
                        "{%0,%1,%2,%3},{%4,%5,%6,%7},{%8,%9},{%0,%1,%2,%3};"
                        : "+f"(c[mi][ni][0]), "+f"(c[mi][ni][1]),
                          "+f"(c[mi][ni][2]), "+f"(c[mi][ni][3])
                        : "r"(a[mi][0]), "r"(a[mi][1]), "r"(a[mi][2]), "r"(a[mi][3]),
                          "r"(b[ni][0]), "r"(b[ni][1]));
                }
        }
    };

    const int nt = K >> 4;
    load_tiles(0, 0);
    for (int t = 0; t < nt; t++) {
        const int buf = t & 1;
        if (t + 1 < nt) {
            load_tiles((t + 1) << 4, 1 - buf);
            asm volatile("cp.async.wait_group 1;\n");
        } else {
            asm volatile("cp.async.wait_group 0;\n");
        }
        __syncthreads();
        compute(buf);
        __syncthreads();
    }

    // epilogue
    #pragma unroll
    for (int mi = 0; mi < 2; mi++) {
        #pragma unroll
        for (int ni = 0; ni < 4; ni++) {
            int col = n0 + wn*32 + ni*8 + 2*qd;
            float bsum0 = bias ? bias[col]     : 0.0f;
            float bsum1 = bias ? bias[col + 1] : 0.0f;
            #pragma unroll
            for (int rr = 0; rr < 2; rr++) {
                int row = m0 + wm*32 + mi*16 + grp + rr*8;
                if (row >= M) continue;
                float v0 = c[mi][ni][rr*2 + 0] + bsum0;
                float v1 = c[mi][ni][rr*2 + 1] + bsum1;
                if (DO_GELU) { v0 = gelu_exact(v0); v1 = gelu_exact(v1); }
                if (DO_RES) {
                    const float2 rv = *reinterpret_cast<const float2*>(&res[(long)row*ldo + col]);
                    v0 += rv.x; v1 += rv.y;
                }
                float2 ov; ov.x = v0; ov.y = v1;
                *reinterpret_cast<float2*>(&out[(long)row*ldo + col]) = ov;
            }
        }
    }
}

// ---------------- attention: one block per (b,h,q), 128 threads ----------------
// reads packed qkv: row stride 768, q at +0, k at +256, v at +512
__global__ void attn_kernel(int adaptive) {
    int qt = blockIdx.x;
    int bh = blockIdx.y;
    int b = bh >> 3, h = bh & 7;
    int tid = threadIdx.x;
    __shared__ float4 sq4[DHH/4];
    __shared__ float sc[TT + 5];
    __shared__ float red[128];
    __shared__ float red2[4][DHH];
    const float scale = 0.1767766952966369f;  // 1/sqrt(32)

    if (tid < DHH/4) sq4[tid] = reinterpret_cast<const float4*>(
        &g_qkv[((long)(b*TT + qt))*QKVN + h*DHH])[tid];
    __syncthreads();

    int nk = qt + 1;
    float lmax = -1e30f;
    for (int kt = tid; kt < nk; kt += 128) {
        const float4* kr = reinterpret_cast<const float4*>(
            &g_qkv[((long)(b*TT + kt))*QKVN + 256 + h*DHH]);
        float s = 0.0f;
        #pragma unroll
        for (int d = 0; d < DHH/4; d++) {
            float4 kv = kr[d], qv = sq4[d];
            s += qv.x*kv.x + qv.y*kv.y + qv.z*kv.z + qv.w*kv.w;
        }
        s *= scale;
        if (adaptive) s += g_h[((long)b*TT + qt)*TT + kt];
        sc[kt] = s;
        lmax = fmaxf(lmax, s);
    }
    red[tid] = lmax; __syncthreads();
    for (int st = 64; st > 0; st >>= 1) { if (tid < st) red[tid] = fmaxf(red[tid], red[tid + st]); __syncthreads(); }
    float m = red[0]; __syncthreads();

    float lsum = 0.0f;
    for (int kt = tid; kt < nk; kt += 128) {
        float p = __expf(sc[kt] - m);
        sc[kt] = p;
        lsum += p;
    }
    red[tid] = lsum; __syncthreads();
    for (int st = 64; st > 0; st >>= 1) { if (tid < st) red[tid] += red[tid + st]; __syncthreads(); }
    float inv = 1.0f / red[0];
    __syncthreads();

    int d = tid & 31, g = tid >> 5;
    float acc = 0.0f;
    for (int kt = g; kt < nk; kt += 4) {
        acc += sc[kt] * g_qkv[((long)(b*TT + kt))*QKVN + 512 + h*DHH + d];
    }
    red2[g][d] = acc; __syncthreads();
    if (g == 0) {
        float yv = (red2[0][d] + red2[1][d] + red2[2][d] + red2[3][d]) * inv;
        g_y[((long)(b*TT + qt))*CC + h*DHH + d] = yv;
    }
}

// ---------------- launch ----------------
extern "C" void kernel_launch(void* const* d_in, const int* in_sizes, int n_in,
                              void* d_out, int out_size) {
    const float* dc      = (const float*)d_in[0];
    const float* z       = (const float*)d_in[1];
    const float* p1      = (const float*)d_in[2];
    const float* p2      = (const float*)d_in[3];
    const float* p3      = (const float*)d_in[4];
    const float* frame   = (const float*)d_in[5];
    const float* cam     = (const float*)d_in[6];
    const float* timee   = (const float*)d_in[7];
    const float* locW1   = (const float*)d_in[8];
    const float* locb1   = (const float*)d_in[9];
    const float* locW2   = (const float*)d_in[10];
    const float* locb2   = (const float*)d_in[11];
    const float* ln1w    = (const float*)d_in[12];
    const float* ln1b    = (const float*)d_in[13];
    const float* Wq      = (const float*)d_in[14];
    const float* bq      = (const float*)d_in[15];
    const float* Wk      = (const float*)d_in[16];
    const float* bk      = (const float*)d_in[17];
    const float* Wv      = (const float*)d_in[18];
    const float* bv      = (const float*)d_in[19];
    const float* Wo      = (const float*)d_in[20];
    const float* bo      = (const float*)d_in[21];
    const float* ln2w    = (const float*)d_in[22];
    const float* ln2b    = (const float*)d_in[23];
    const float* W1      = (const float*)d_in[24];
    const float* b1      = (const float*)d_in[25];
    const float* W2      = (const float*)d_in[26];
    const float* b2      = (const float*)d_in[27];
    const float* lnfw    = (const float*)d_in[28];
    const float* lnfb    = (const float*)d_in[29];
    const float* headW   = (const float*)d_in[30];

    float *xp, *xnp, *qkvp, *yp, *ffnp, *wqkvp, *bqkvp;
    cudaGetSymbolAddress((void**)&xp,    g_x);
    cudaGetSymbolAddress((void**)&xnp,   g_xn);
    cudaGetSymbolAddress((void**)&qkvp,  g_qkv);
    cudaGetSymbolAddress((void**)&yp,    g_y);
    cudaGetSymbolAddress((void**)&ffnp,  g_ffn);
    cudaGetSymbolAddress((void**)&wqkvp, g_wqkv);
    cudaGetSymbolAddress((void**)&bqkvp, g_bqkv);

    // pack fused QKV weights/biases
    {
        long nw = (long)LL*QKVN*CC;
        pack_qkv_w<<<(int)((nw + 255) / 256), 256>>>(Wq, Wk, Wv);
        pack_qkv_b<<<(LL*QKVN + 255) / 256, 256>>>(bq, bk, bv);
    }

    // attention bias h
    {
        long nh = (long)BB*TT*TT;
        zero_h_kernel<<<(int)((nh + 255) / 256), 256>>>();
        loc1_kernel<<<3*BB, 64>>>(p1, p2, p3, locW1, locb1);
        loc2_kernel<<<(3*BB*65536 + 127) / 128, 128>>>(locW2, locb2);
    }

    embed_kernel<<<(MM*CC + 255) / 256, 256>>>(dc, z, frame, cam, timee);

    const int MB = (MM + 127) / 128;     // 26
    dim3 g_qkvg(QKVN/64, MB);
    dim3 g_cc(CC/64, MB);
    dim3 g_ff(FF/64, MB);
    dim3 attn_grid(TT, BB*HH);

    for (int l = 0; l < LL; l++) {
        ln_kernel<<<MM, CC>>>(xp, ln1w + l*CC, ln1b + l*CC, xnp);

        gemm_tc<false,false><<<g_qkvg, 256>>>(xnp, CC, wqkvp + (long)l*QKVN*CC,
                                              bqkvp + l*QKVN, nullptr, qkvp, QKVN,
                                              MM, QKVN, CC);

        attn_kernel<<<attn_grid, 128>>>((l % 2 == 0) ? 1 : 0);

        gemm_tc<false,true><<<g_cc, 256>>>(yp, CC, Wo + (long)l*CC*CC, bo + l*CC,
                                           xp, xp, CC, MM, CC, CC);

        ln_kernel<<<MM, CC>>>(xp, ln2w + l*CC, ln2b + l*CC, xnp);

        gemm_tc<true,false><<<g_ff, 256>>>(xnp, CC, W1 + (long)l*FF*CC, b1 + (long)l*FF,
                                           nullptr, ffnp, FF, MM, FF, CC);
        gemm_tc<false,true><<<g_cc, 256>>>(ffnp, FF, W2 + (long)l*CC*FF, b2 + l*CC,
                                           xp, xp, CC, MM, CC, FF);
    }

    ln_kernel<<<MM, CC>>>(xp, lnfw, lnfb, xnp);

    dim3 g_head(VOC/64, MB);
    gemm_tc<false,false><<<g_head, 256>>>(xnp, CC, headW, nullptr, nullptr,
                                          (float*)d_out, VOC, MM, VOC, CC);
}

// round 6
// speedup vs baseline: 8.5796x; 1.9396x over previous
#include <cuda_runtime.h>
#include <math.h>

// ---------------- problem constants ----------------
#define BB   4
#define TT   827
#define CC   256
#define HH   8
#define DHH  32
#define LL   12
#define FF   1024            // 4*C
#define MM   (BB*TT)         // 3308 rows
#define VOC  16384
#define QKVN 768

// ---------------- scratch (device globals; no allocs allowed) ----------------
__device__ float g_x   [MM*CC];
__device__ float g_xn  [MM*CC];
__device__ float g_qkv [MM*QKVN];
__device__ float g_y   [MM*CC];
__device__ float g_ffn [MM*FF];
__device__ float g_h   [(long)BB*TT*TT];   // additive attention bias (even layers)
__device__ float g_z1  [3*BB*60];
__device__ float g_wqkv[(long)LL*QKVN*CC]; // packed [l][n(768)][k(256)]
__device__ float g_bqkv[LL*QKVN];

__device__ __forceinline__ float gelu_exact(float z) {
    return 0.5f * z * (1.0f + erff(z * 0.70710678118654752f));
}

__device__ __forceinline__ unsigned f2tf32(float x) {
    unsigned r;
    asm("cvt.rna.tf32.f32 %0, %1;" : "=r"(r) : "f"(x));
    return r;
}

// ---------------- fused QKV weight+bias packing ----------------
__global__ void pack_qkv_kernel(const float* __restrict__ Wq, const float* __restrict__ Wk,
                                const float* __restrict__ Wv, const float* __restrict__ bq,
                                const float* __restrict__ bk, const float* __restrict__ bv) {
    const long nw = (long)LL*QKVN*CC;
    long idx = (long)blockIdx.x * blockDim.x + threadIdx.x;
    if (idx < nw) {
        int k = (int)(idx % CC);
        int n = (int)((idx / CC) % QKVN);
        int l = (int)(idx / ((long)CC*QKVN));
        const float* src;
        if      (n < 256) src = &Wq[((long)l*256 + n      )*CC];
        else if (n < 512) src = &Wk[((long)l*256 + n - 256)*CC];
        else              src = &Wv[((long)l*256 + n - 512)*CC];
        g_wqkv[idx] = src[k];
    } else if (idx < nw + (long)LL*QKVN) {
        int r = (int)(idx - nw);
        int n = r % QKVN;
        int l = r / QKVN;
        float v;
        if      (n < 256) v = bq[l*256 + n];
        else if (n < 512) v = bk[l*256 + n - 256];
        else              v = bv[l*256 + n - 512];
        g_bqkv[r] = v;
    }
}

// ---------------- locality MLP ----------------
__global__ void loc1_kernel(const float* __restrict__ p1, const float* __restrict__ p2,
                            const float* __restrict__ p3, const float* __restrict__ W1,
                            const float* __restrict__ b1) {
    int mat = blockIdx.x / BB;
    int b   = blockIdx.x % BB;
    int j   = threadIdx.x;
    if (j >= 60) return;
    const float* p = (mat == 0) ? p1 : (mat == 1) ? p2 : p3;
    float s = b1[j];
    #pragma unroll
    for (int i = 0; i < 30; i++) s += p[b*30 + i] * W1[j*30 + i];
    g_z1[(mat*BB + b)*60 + j] = gelu_exact(s);
}

__global__ void zero_h_kernel() {
    long i = (long)blockIdx.x * blockDim.x + threadIdx.x;
    if (i < (long)BB*TT*TT) g_h[i] = 0.0f;
}

__global__ void loc2_kernel(const float* __restrict__ W2, const float* __restrict__ b2) {
    int idx = blockIdx.x * blockDim.x + threadIdx.x;
    const int total = 3 * BB * 65536;
    if (idx >= total) return;
    int mat = idx / (BB * 65536);
    int rem = idx % (BB * 65536);
    int b   = rem / 65536;
    int o   = rem % 65536;
    const float* z1 = &g_z1[(mat*BB + b)*60];
    const float* wr = &W2[(long)o * 60];
    float s = b2[o];
    #pragma unroll
    for (int j = 0; j < 60; j++) s += z1[j] * wr[j];
    int r = o >> 8, c = o & 255;
    int r0 = (mat == 0) ? 285 : 571;
    int c0 = (mat == 2) ? 286 : 0;
    g_h[((long)b*TT + (r0 + r))*TT + (c0 + c)] = s;
}

// ---------------- embedding ----------------
__global__ void embed_kernel(const float* __restrict__ dc, const float* __restrict__ z,
                             const float* __restrict__ frame, const float* __restrict__ cam,
                             const float* __restrict__ timee) {
    int idx = blockIdx.x * blockDim.x + threadIdx.x;
    if (idx >= MM*CC) return;
    int c = idx % CC;
    int t = (idx / CC) % TT;
    int b = idx / (CC * TT);
    float tok = (t < 572) ? dc[((long)b*572 + t)*CC + c]
                          : z [((long)b*256 + (t - 572))*CC + c];
    float role;
    if      (t < 256) role = frame[(t      )*CC + c];
    else if (t < 286) role = cam  [(t - 256)*CC + c];
    else if (t < 542) role = frame[(t - 286)*CC + c];
    else if (t < 572) role = cam  [(t - 542)*CC + c];
    else              role = frame[(t - 572)*CC + c];
    g_x[idx] = tok + role + timee[t*CC + c];
}

// ---------------- layernorm (warp-shuffle reductions) ----------------
__global__ void __launch_bounds__(CC) ln_kernel(const float* __restrict__ x,
                                                const float* __restrict__ w,
                                                const float* __restrict__ b,
                                                float* __restrict__ out) {
    int row = blockIdx.x;
    int tid = threadIdx.x;
    __shared__ float ws[8];
    __shared__ float mv[2];
    float v = x[(long)row*CC + tid];

    float s = v;
    #pragma unroll
    for (int o = 16; o; o >>= 1) s += __shfl_xor_sync(0xffffffffu, s, o);
    if ((tid & 31) == 0) ws[tid >> 5] = s;
    __syncthreads();
    if (tid < 32) {
        float t2 = (tid < 8) ? ws[tid] : 0.0f;
        #pragma unroll
        for (int o = 4; o; o >>= 1) t2 += __shfl_xor_sync(0xffffffffu, t2, o);
        if (tid == 0) mv[0] = t2 * (1.0f / CC);
    }
    __syncthreads();
    float mean = mv[0];
    float d = v - mean;
    s = d * d;
    #pragma unroll
    for (int o = 16; o; o >>= 1) s += __shfl_xor_sync(0xffffffffu, s, o);
    if ((tid & 31) == 0) ws[tid >> 5] = s;
    __syncthreads();
    if (tid < 32) {
        float t2 = (tid < 8) ? ws[tid] : 0.0f;
        #pragma unroll
        for (int o = 4; o; o >>= 1) t2 += __shfl_xor_sync(0xffffffffu, t2, o);
        if (tid == 0) mv[1] = t2 * (1.0f / CC);
    }
    __syncthreads();
    out[(long)row*CC + tid] = d * rsqrtf(mv[1] + 1e-5f) * w[tid] + b[tid];
}

// ---------------- tensor-core TF32 GEMM (R3-proven 2-stage pipeline) ----------------
// A: (M,K) row-major lda; W: (N,K) row-major; out: (M,ldo)
// Tile 128x64x16, 256 threads = 8 warps (4 m x 2 n), warp does 32x32 via m16n8k8.
#define SM_STRIDE 20   // floats; 16B-aligned rows AND conflict-free fragment reads

__device__ __forceinline__ void cp_async16(unsigned dst, const void* src, int bytes) {
    asm volatile("cp.async.ca.shared.global [%0], [%1], 16, %2;\n"
                 :: "r"(dst), "l"(src), "r"(bytes));
}

template<bool DO_GELU, bool DO_RES>
__global__ void __launch_bounds__(256)
gemm_tc(const float* __restrict__ A, int lda,
        const float* __restrict__ W,
        const float* __restrict__ bias,
        const float* __restrict__ res,
        float* __restrict__ out, int ldo,
        int M, int N, int K) {
    __shared__ __align__(16) float As[2][128*SM_STRIDE];
    __shared__ __align__(16) float Bs[2][64*SM_STRIDE];

    const int tid  = threadIdx.x;
    const int m0   = blockIdx.y * 128;
    const int n0   = blockIdx.x * 64;
    const int warp = tid >> 5, lane = tid & 31;
    const int wm = warp >> 1, wn = warp & 1;
    const int grp = lane >> 2, qd = lane & 3;

    float c[2][4][4];
    #pragma unroll
    for (int i = 0; i < 2; i++)
        #pragma unroll
        for (int j = 0; j < 4; j++)
            #pragma unroll
            for (int k = 0; k < 4; k++) c[i][j][k] = 0.0f;

    const int a_r0 = tid >> 2,         a_c0 = (tid & 3) << 2;
    const int a_r1 = (tid + 256) >> 2, a_c1 = (tid & 3) << 2;
    const int b_r  = tid >> 2,         b_c  = (tid & 3) << 2;

    unsigned sA[2], sB[2];
    sA[0] = (unsigned)__cvta_generic_to_shared(&As[0][0]);
    sA[1] = (unsigned)__cvta_generic_to_shared(&As[1][0]);
    sB[0] = (unsigned)__cvta_generic_to_shared(&Bs[0][0]);
    sB[1] = (unsigned)__cvta_generic_to_shared(&Bs[1][0]);

    auto load_tiles = [&](int k0, int buf) {
        int m = m0 + a_r0;
        const float* src = A + (long)(m < M ? m : 0) * lda + k0 + a_c0;
        cp_async16(sA[buf] + (a_r0*SM_STRIDE + a_c0)*4, src, m < M ? 16 : 0);
        m = m0 + a_r1;
        src = A + (long)(m < M ? m : 0) * lda + k0 + a_c1;
        cp_async16(sA[buf] + (a_r1*SM_STRIDE + a_c1)*4, src, m < M ? 16 : 0);
        const float* srcb = W + (long)(n0 + b_r) * K + k0 + b_c;
        cp_async16(sB[buf] + (b_r*SM_STRIDE + b_c)*4, srcb, 16);
        asm volatile("cp.async.commit_group;\n");
    };

    auto compute = [&](int buf) {
        const float* pa = As[buf];
        const float* pb = Bs[buf];
        #pragma unroll
        for (int ks = 0; ks < 2; ks++) {
            const int kk = ks * 8;
            unsigned a[2][4], b[4][2];
            #pragma unroll
            for (int mi = 0; mi < 2; mi++) {
                int r = wm*32 + mi*16 + grp;
                a[mi][0] = f2tf32(pa[(r    )*SM_STRIDE + kk + qd    ]);
                a[mi][1] = f2tf32(pa[(r + 8)*SM_STRIDE + kk + qd    ]);
                a[mi][2] = f2tf32(pa[(r    )*SM_STRIDE + kk + qd + 4]);
                a[mi][3] = f2tf32(pa[(r + 8)*SM_STRIDE + kk + qd + 4]);
            }
            #pragma unroll
            for (int ni = 0; ni < 4; ni++) {
                int n = wn*32 + ni*8 + grp;
                b[ni][0] = f2tf32(pb[n*SM_STRIDE + kk + qd    ]);
                b[ni][1] = f2tf32(pb[n*SM_STRIDE + kk + qd + 4]);
            }
            #pragma unroll
            for (int mi = 0; mi < 2; mi++)
                #pragma unroll
                for (int ni = 0; ni < 4; ni++) {
                    asm volatile(
                        "mma.sync.aligned.m16n8k8.row.col.f32.tf32.tf32.f32 "
                        "{%0,%1,%2,%3},{%4,%5,%6,%7},{%8,%9},{%0,%1,%2,%3};"
                        : "+f"(c[mi][ni][0]), "+f"(c[mi][ni][1]),
                          "+f"(c[mi][ni][2]), "+f"(c[mi][ni][3])
                        : "r"(a[mi][0]), "r"(a[mi][1]), "r"(a[mi][2]), "r"(a[mi][3]),
                          "r"(b[ni][0]), "r"(b[ni][1]));
                }
        }
    };

    const int nt = K >> 4;
    load_tiles(0, 0);
    for (int t = 0; t < nt; t++) {
        const int buf = t & 1;
        if (t + 1 < nt) {
            load_tiles((t + 1) << 4, 1 - buf);
            asm volatile("cp.async.wait_group 1;\n");
        } else {
            asm volatile("cp.async.wait_group 0;\n");
        }
        __syncthreads();
        compute(buf);
        __syncthreads();
    }

    // epilogue
    #pragma unroll
    for (int mi = 0; mi < 2; mi++) {
        #pragma unroll
        for (int ni = 0; ni < 4; ni++) {
            int col = n0 + wn*32 + ni*8 + 2*qd;
            float bsum0 = bias ? bias[col]     : 0.0f;
            float bsum1 = bias ? bias[col + 1] : 0.0f;
            #pragma unroll
            for (int rr = 0; rr < 2; rr++) {
                int row = m0 + wm*32 + mi*16 + grp + rr*8;
                if (row >= M) continue;
                float v0 = c[mi][ni][rr*2 + 0] + bsum0;
                float v1 = c[mi][ni][rr*2 + 1] + bsum1;
                if (DO_GELU) { v0 = gelu_exact(v0); v1 = gelu_exact(v1); }
                if (DO_RES) {
                    const float2 rv = *reinterpret_cast<const float2*>(&res[(long)row*ldo + col]);
                    v0 += rv.x; v1 += rv.y;
                }
                float2 ov; ov.x = v0; ov.y = v1;
                *reinterpret_cast<float2*>(&out[(long)row*ldo + col]) = ov;
            }
        }
    }
}

// ---------------- flash-style attention ----------------
// block = (b, h, tile of 64 queries), 256 threads. All math fp32.
// All smem arrays explicitly 16B-aligned (vector access safety).
#define ATQ 64
#define ATK 64

__global__ void __launch_bounds__(256) attn_kernel(int adaptive) {
    __shared__ __align__(16) float Qs[ATQ*33];
    __shared__ __align__(16) float Ks[ATK*33];
    __shared__ __align__(16) float Vs[ATK*36];
    __shared__ __align__(16) float Ps[ATQ*65];

    const int tile = blockIdx.x;
    const int bh   = blockIdx.y;
    const int b = bh >> 3, h = bh & 7;
    const int t = threadIdx.x;
    const int q0 = tile * ATQ;
    const float scale = 0.1767766952966369f;   // 1/sqrt(32)

    const int rv  = t >> 2;        // 0..63  (row id for loads, q id for PV)
    const int sub = t & 3;         // quad id
    const int qi  = t >> 4;        // 0..15  (score pass)
    const int ki  = t & 15;

    // load Q tile once
    {
        int r = q0 + rv;
        float4 a0 = {0,0,0,0}, a1 = {0,0,0,0};
        if (r < TT) {
            const float4* src = reinterpret_cast<const float4*>(
                &g_qkv[((long)(b*TT + r))*QKVN + h*DHH + sub*8]);
            a0 = src[0]; a1 = src[1];
        }
        int base = rv*33 + sub*8;
        Qs[base+0]=a0.x; Qs[base+1]=a0.y; Qs[base+2]=a0.z; Qs[base+3]=a0.w;
        Qs[base+4]=a1.x; Qs[base+5]=a1.y; Qs[base+6]=a1.z; Qs[base+7]=a1.w;
    }

    float acc[8] = {0,0,0,0,0,0,0,0};
    float m_run = -1e30f, l_run = 0.0f;
    const int my_q = q0 + rv;

    const int ntile = tile + 1;
    for (int kt_t = 0; kt_t < ntile; kt_t++) {
        const int k0 = kt_t * ATK;
        __syncthreads();   // previous tile fully consumed

        // load K and V tiles
        {
            int r = k0 + rv;
            float4 kv0 = {0,0,0,0}, kv1 = {0,0,0,0}, vv0 = {0,0,0,0}, vv1 = {0,0,0,0};
            if (r < TT) {
                const float4* ks = reinterpret_cast<const float4*>(
                    &g_qkv[((long)(b*TT + r))*QKVN + 256 + h*DHH + sub*8]);
                kv0 = ks[0]; kv1 = ks[1];
                const float4* vs = reinterpret_cast<const float4*>(
                    &g_qkv[((long)(b*TT + r))*QKVN + 512 + h*DHH + sub*8]);
                vv0 = vs[0]; vv1 = vs[1];
            }
            int kb = rv*33 + sub*8;
            Ks[kb+0]=kv0.x; Ks[kb+1]=kv0.y; Ks[kb+2]=kv0.z; Ks[kb+3]=kv0.w;
            Ks[kb+4]=kv1.x; Ks[kb+5]=kv1.y; Ks[kb+6]=kv1.z; Ks[kb+7]=kv1.w;
            float4* vd = reinterpret_cast<float4*>(&Vs[rv*36 + sub*8]);
            vd[0] = vv0; vd[1] = vv1;
        }
        __syncthreads();

        // score pass: 4x4 register block
        float s[4][4] = {{0,0,0,0},{0,0,0,0},{0,0,0,0},{0,0,0,0}};
        #pragma unroll 8
        for (int d = 0; d < 32; d++) {
            float qa[4], kb[4];
            #pragma unroll
            for (int j = 0; j < 4; j++) {
                qa[j] = Qs[(qi*4 + j)*33 + d];
                kb[j] = Ks[(ki*4 + j)*33 + d];
            }
            #pragma unroll
            for (int a = 0; a < 4; a++)
                #pragma unroll
                for (int cc2 = 0; cc2 < 4; cc2++)
                    s[a][cc2] += qa[a] * kb[cc2];
        }
        const bool diag = (kt_t == tile);
        #pragma unroll
        for (int a = 0; a < 4; a++) {
            int q = q0 + qi*4 + a;
            #pragma unroll
            for (int cc2 = 0; cc2 < 4; cc2++) {
                int kk = k0 + ki*4 + cc2;
                float val;
                bool masked = diag && (kk > q);
                if (masked) {
                    val = -1e30f;
                } else {
                    float bias = (adaptive && q < TT) ? g_h[((long)b*TT + q)*TT + kk] : 0.0f;
                    val = s[a][cc2]*scale + bias;
                }
                Ps[(qi*4 + a)*65 + ki*4 + cc2] = val;
            }
        }
        __syncthreads();

        // online softmax update (4 threads per q, quad shuffles)
        const int pb = rv*65 + sub*16;
        float tmax = -1e30f;
        #pragma unroll
        for (int j = 0; j < 16; j++) tmax = fmaxf(tmax, Ps[pb + j]);
        tmax = fmaxf(tmax, __shfl_xor_sync(0xffffffffu, tmax, 1));
        tmax = fmaxf(tmax, __shfl_xor_sync(0xffffffffu, tmax, 2));
        float m_new = fmaxf(m_run, tmax);
        float corr = __expf(m_run - m_new);
        float tsum = 0.0f;
        #pragma unroll
        for (int j = 0; j < 16; j++) {
            float p = __expf(Ps[pb + j] - m_new);
            Ps[pb + j] = p;
            tsum += p;
        }
        tsum += __shfl_xor_sync(0xffffffffu, tsum, 1);
        tsum += __shfl_xor_sync(0xffffffffu, tsum, 2);
        l_run = l_run * corr + tsum;
        m_run = m_new;
        #pragma unroll
        for (int j = 0; j < 8; j++) acc[j] *= corr;

        // PV accumulate
        const float* pr = &Ps[rv*65];
        #pragma unroll 4
        for (int kk = 0; kk < ATK; kk++) {
            float p = pr[kk];
            const float4* vr = reinterpret_cast<const float4*>(&Vs[kk*36 + sub*8]);
            float4 v0 = vr[0], v1 = vr[1];
            acc[0] += p*v0.x; acc[1] += p*v0.y; acc[2] += p*v0.z; acc[3] += p*v0.w;
            acc[4] += p*v1.x; acc[5] += p*v1.y; acc[6] += p*v1.z; acc[7] += p*v1.w;
        }
    }

    if (my_q < TT) {
        float inv = 1.0f / l_run;
        float4 o0, o1;
        o0.x = acc[0]*inv; o0.y = acc[1]*inv; o0.z = acc[2]*inv; o0.w = acc[3]*inv;
        o1.x = acc[4]*inv; o1.y = acc[5]*inv; o1.z = acc[6]*inv; o1.w = acc[7]*inv;
        float4* dst = reinterpret_cast<float4*>(
            &g_y[((long)(b*TT + my_q))*CC + h*DHH + sub*8]);
        dst[0] = o0; dst[1] = o1;
    }
}

// ---------------- launch ----------------
extern "C" void kernel_launch(void* const* d_in, const int* in_sizes, int n_in,
                              void* d_out, int out_size) {
    const float* dc      = (const float*)d_in[0];
    const float* z       = (const float*)d_in[1];
    const float* p1      = (const float*)d_in[2];
    const float* p2      = (const float*)d_in[3];
    const float* p3      = (const float*)d_in[4];
    const float* frame   = (const float*)d_in[5];
    const float* cam     = (const float*)d_in[6];
    const float* timee   = (const float*)d_in[7];
    const float* locW1   = (const float*)d_in[8];
    const float* locb1   = (const float*)d_in[9];
    const float* locW2   = (const float*)d_in[10];
    const float* locb2   = (const float*)d_in[11];
    const float* ln1w    = (const float*)d_in[12];
    const float* ln1b    = (const float*)d_in[13];
    const float* Wq      = (const float*)d_in[14];
    const float* bq      = (const float*)d_in[15];
    const float* Wk      = (const float*)d_in[16];
    const float* bk      = (const float*)d_in[17];
    const float* Wv      = (const float*)d_in[18];
    const float* bv      = (const float*)d_in[19];
    const float* Wo      = (const float*)d_in[20];
    const float* bo      = (const float*)d_in[21];
    const float* ln2w    = (const float*)d_in[22];
    const float* ln2b    = (const float*)d_in[23];
    const float* W1      = (const float*)d_in[24];
    const float* b1      = (const float*)d_in[25];
    const float* W2      = (const float*)d_in[26];
    const float* b2      = (const float*)d_in[27];
    const float* lnfw    = (const float*)d_in[28];
    const float* lnfb    = (const float*)d_in[29];
    const float* headW   = (const float*)d_in[30];

    float *xp, *xnp, *qkvp, *yp, *ffnp, *wqkvp, *bqkvp;
    cudaGetSymbolAddress((void**)&xp,    g_x);
    cudaGetSymbolAddress((void**)&xnp,   g_xn);
    cudaGetSymbolAddress((void**)&qkvp,  g_qkv);
    cudaGetSymbolAddress((void**)&yp,    g_y);
    cudaGetSymbolAddress((void**)&ffnp,  g_ffn);
    cudaGetSymbolAddress((void**)&wqkvp, g_wqkv);
    cudaGetSymbolAddress((void**)&bqkvp, g_bqkv);

    const int MB = (MM + 127) / 128;     // 26
    dim3 g_qkvg(QKVN/64, MB);
    dim3 g_cc(CC/64, MB);
    dim3 g_ff(FF/64, MB);
    dim3 attn_grid((TT + ATQ - 1)/ATQ, BB*HH);   // (13, 32)

    // launches 1..3: pack, embed, ln  → launch #4 is gemm_tc (ncu capture target)
    {
        long np = (long)LL*QKVN*CC + (long)LL*QKVN;
        pack_qkv_kernel<<<(int)((np + 255) / 256), 256>>>(Wq, Wk, Wv, bq, bk, bv);
    }
    embed_kernel<<<(MM*CC + 255) / 256, 256>>>(dc, z, frame, cam, timee);

    for (int l = 0; l < LL; l++) {
        ln_kernel<<<MM, CC>>>(xp, ln1w + l*CC, ln1b + l*CC, xnp);

        gemm_tc<false,false><<<g_qkvg, 256>>>(xnp, CC, wqkvp + (long)l*QKVN*CC,
                                              bqkvp + l*QKVN, nullptr, qkvp, QKVN,
                                              MM, QKVN, CC);

        if (l == 0) {
            // h bias build (needed before first attention only)
            long nh = (long)BB*TT*TT;
            zero_h_kernel<<<(int)((nh + 255) / 256), 256>>>();
            loc1_kernel<<<3*BB, 64>>>(p1, p2, p3, locW1, locb1);
            loc2_kernel<<<(3*BB*65536 + 127) / 128, 128>>>(locW2, locb2);
        }

        attn_kernel<<<attn_grid, 256>>>((l % 2 == 0) ? 1 : 0);

        gemm_tc<false,true><<<g_cc, 256>>>(yp, CC, Wo + (long)l*CC*CC, bo + l*CC,
                                           xp, xp, CC, MM, CC, CC);

        ln_kernel<<<MM, CC>>>(xp, ln2w + l*CC, ln2b + l*CC, xnp);

        gemm_tc<true,false><<<g_ff, 256>>>(xnp, CC, W1 + (long)l*FF*CC, b1 + (long)l*FF,
                                           nullptr, ffnp, FF, MM, FF, CC);
        gemm_tc<false,true><<<g_cc, 256>>>(ffnp, FF, W2 + (long)l*CC*FF, b2 + l*CC,
                                           xp, xp, CC, MM, CC, FF);
    }

    ln_kernel<<<MM, CC>>>(xp, lnfw, lnfb, xnp);

    dim3 g_head(VOC/64, MB);
    gemm_tc<false,false><<<g_head, 256>>>(xnp, CC, headW, nullptr, nullptr,
                                          (float*)d_out, VOC, MM, VOC, CC);
}

// round 8
// speedup vs baseline: 12.6770x; 1.4776x over previous
#include <cuda_runtime.h>
#include <math.h>

// ---------------- problem constants ----------------
#define BB   4
#define TT   827
#define CC   256
#define HH   8
#define DHH  32
#define LL   12
#define FF   1024            // 4*C
#define MM   (BB*TT)         // 3308 rows
#define VOC  16384
#define QKVN 768

// ---------------- scratch (device globals; no allocs allowed) ----------------
__device__ float g_x   [MM*CC];
__device__ float g_xn  [MM*CC];
__device__ float g_qkv [MM*QKVN];
__device__ float g_y   [MM*CC];
__device__ float g_ffn [MM*FF];
__device__ float g_h   [(long)BB*TT*TT];   // additive attention bias (even layers)
__device__ float g_z1  [3*BB*60];
__device__ float g_wqkv[(long)LL*QKVN*CC]; // packed [l][n(768)][k(256)]
__device__ float g_bqkv[LL*QKVN];

__device__ __forceinline__ float gelu_exact(float z) {
    return 0.5f * z * (1.0f + erff(z * 0.70710678118654752f));
}

__device__ __forceinline__ unsigned f2tf32(float x) {
    unsigned r;
    asm("cvt.rna.tf32.f32 %0, %1;" : "=r"(r) : "f"(x));
    return r;
}

__device__ __forceinline__ void mma_tf32(float c[4], const unsigned a[4],
                                         unsigned b0, unsigned b1) {
    asm volatile(
        "mma.sync.aligned.m16n8k8.row.col.f32.tf32.tf32.f32 "
        "{%0,%1,%2,%3},{%4,%5,%6,%7},{%8,%9},{%0,%1,%2,%3};"
        : "+f"(c[0]), "+f"(c[1]), "+f"(c[2]), "+f"(c[3])
        : "r"(a[0]), "r"(a[1]), "r"(a[2]), "r"(a[3]), "r"(b0), "r"(b1));
}

// ---------------- fused QKV weight+bias packing ----------------
__global__ void pack_qkv_kernel(const float* __restrict__ Wq, const float* __restrict__ Wk,
                                const float* __restrict__ Wv, const float* __restrict__ bq,
                                const float* __restrict__ bk, const float* __restrict__ bv) {
    const long nw = (long)LL*QKVN*CC;
    long idx = (long)blockIdx.x * blockDim.x + threadIdx.x;
    if (idx < nw) {
        int k = (int)(idx % CC);
        int n = (int)((idx / CC) % QKVN);
        int l = (int)(idx / ((long)CC*QKVN));
        const float* src;
        if      (n < 256) src = &Wq[((long)l*256 + n      )*CC];
        else if (n < 512) src = &Wk[((long)l*256 + n - 256)*CC];
        else              src = &Wv[((long)l*256 + n - 512)*CC];
        g_wqkv[idx] = src[k];
    } else if (idx < nw + (long)LL*QKVN) {
        int r = (int)(idx - nw);
        int n = r % QKVN;
        int l = r / QKVN;
        float v;
        if      (n < 256) v = bq[l*256 + n];
        else if (n < 512) v = bk[l*256 + n - 256];
        else              v = bv[l*256 + n - 512];
        g_bqkv[r] = v;
    }
}

// ---------------- locality MLP ----------------
__global__ void loc1_kernel(const float* __restrict__ p1, const float* __restrict__ p2,
                            const float* __restrict__ p3, const float* __restrict__ W1,
                            const float* __restrict__ b1) {
    int mat = blockIdx.x / BB;
    int b   = blockIdx.x % BB;
    int j   = threadIdx.x;
    if (j >= 60) return;
    const float* p = (mat == 0) ? p1 : (mat == 1) ? p2 : p3;
    float s = b1[j];
    #pragma unroll
    for (int i = 0; i < 30; i++) s += p[b*30 + i] * W1[j*30 + i];
    g_z1[(mat*BB + b)*60 + j] = gelu_exact(s);
}

__global__ void zero_h_kernel() {
    long i = (long)blockIdx.x * blockDim.x + threadIdx.x;
    if (i < (long)BB*TT*TT) g_h[i] = 0.0f;
}

__global__ void loc2_kernel(const float* __restrict__ W2, const float* __restrict__ b2) {
    int idx = blockIdx.x * blockDim.x + threadIdx.x;
    const int total = 3 * BB * 65536;
    if (idx >= total) return;
    int mat = idx / (BB * 65536);
    int rem = idx % (BB * 65536);
    int b   = rem / 65536;
    int o   = rem % 65536;
    const float* z1 = &g_z1[(mat*BB + b)*60];
    const float* wr = &W2[(long)o * 60];
    float s = b2[o];
    #pragma unroll
    for (int j = 0; j < 60; j++) s += z1[j] * wr[j];
    int r = o >> 8, c = o & 255;
    int r0 = (mat == 0) ? 285 : 571;
    int c0 = (mat == 2) ? 286 : 0;
    g_h[((long)b*TT + (r0 + r))*TT + (c0 + c)] = s;
}

// ---------------- embedding ----------------
__global__ void embed_kernel(const float* __restrict__ dc, const float* __restrict__ z,
                             const float* __restrict__ frame, const float* __restrict__ cam,
                             const float* __restrict__ timee) {
    int idx = blockIdx.x * blockDim.x + threadIdx.x;
    if (idx >= MM*CC) return;
    int c = idx % CC;
    int t = (idx / CC) % TT;
    int b = idx / (CC * TT);
    float tok = (t < 572) ? dc[((long)b*572 + t)*CC + c]
                          : z [((long)b*256 + (t - 572))*CC + c];
    float role;
    if      (t < 256) role = frame[(t      )*CC + c];
    else if (t < 286) role = cam  [(t - 256)*CC + c];
    else if (t < 542) role = frame[(t - 286)*CC + c];
    else if (t < 572) role = cam  [(t - 542)*CC + c];
    else              role = frame[(t - 572)*CC + c];
    g_x[idx] = tok + role + timee[t*CC + c];
}

// ---------------- layernorm (warp-shuffle reductions) ----------------
__global__ void __launch_bounds__(CC) ln_kernel(const float* __restrict__ x,
                                                const float* __restrict__ w,
                                                const float* __restrict__ b,
                                                float* __restrict__ out) {
    int row = blockIdx.x;
    int tid = threadIdx.x;
    __shared__ float ws[8];
    __shared__ float mv[2];
    float v = x[(long)row*CC + tid];

    float s = v;
    #pragma unroll
    for (int o = 16; o; o >>= 1) s += __shfl_xor_sync(0xffffffffu, s, o);
    if ((tid & 31) == 0) ws[tid >> 5] = s;
    __syncthreads();
    if (tid < 32) {
        float t2 = (tid < 8) ? ws[tid] : 0.0f;
        #pragma unroll
        for (int o = 4; o; o >>= 1) t2 += __shfl_xor_sync(0xffffffffu, t2, o);
        if (tid == 0) mv[0] = t2 * (1.0f / CC);
    }
    __syncthreads();
    float mean = mv[0];
    float d = v - mean;
    s = d * d;
    #pragma unroll
    for (int o = 16; o; o >>= 1) s += __shfl_xor_sync(0xffffffffu, s, o);
    if ((tid & 31) == 0) ws[tid >> 5] = s;
    __syncthreads();
    if (tid < 32) {
        float t2 = (tid < 8) ? ws[tid] : 0.0f;
        #pragma unroll
        for (int o = 4; o; o >>= 1) t2 += __shfl_xor_sync(0xffffffffu, t2, o);
        if (tid == 0) mv[1] = t2 * (1.0f / CC);
    }
    __syncthreads();
    out[(long)row*CC + tid] = d * rsqrtf(mv[1] + 1e-5f) * w[tid] + b[tid];
}

// ---------------- tensor-core TF32 GEMM (proven 2-stage pipeline) ----------------
#define SM_STRIDE 20

__device__ __forceinline__ void cp_async16(unsigned dst, const void* src, int bytes) {
    asm volatile("cp.async.ca.shared.global [%0], [%1], 16, %2;\n"
                 :: "r"(dst), "l"(src), "r"(bytes));
}

template<bool DO_GELU, bool DO_RES>
__global__ void __launch_bounds__(256)
gemm_tc(const float* __restrict__ A, int lda,
        const float* __restrict__ W,
        const float* __restrict__ bias,
        const float* __restrict__ res,
        float* __restrict__ out, int ldo,
        int M, int N, int K) {
    __shared__ __align__(16) float As[2][128*SM_STRIDE];
    __shared__ __align__(16) float Bs[2][64*SM_STRIDE];

    const int tid  = threadIdx.x;
    const int m0   = blockIdx.y * 128;
    const int n0   = blockIdx.x * 64;
    const int warp = tid >> 5, lane = tid & 31;
    const int wm = warp >> 1, wn = warp & 1;
    const int grp = lane >> 2, qd = lane & 3;

    float c[2][4][4];
    #pragma unroll
    for (int i = 0; i < 2; i++)
        #pragma unroll
        for (int j = 0; j < 4; j++)
            #pragma unroll
            for (int k = 0; k < 4; k++) c[i][j][k] = 0.0f;

    const int a_r0 = tid >> 2,         a_c0 = (tid & 3) << 2;
    const int a_r1 = (tid + 256) >> 2, a_c1 = (tid & 3) << 2;
    const int b_r  = tid >> 2,         b_c  = (tid & 3) << 2;

    unsigned sA[2], sB[2];
    sA[0] = (unsigned)__cvta_generic_to_shared(&As[0][0]);
    sA[1] = (unsigned)__cvta_generic_to_shared(&As[1][0]);
    sB[0] = (unsigned)__cvta_generic_to_shared(&Bs[0][0]);
    sB[1] = (unsigned)__cvta_generic_to_shared(&Bs[1][0]);

    auto load_tiles = [&](int k0, int buf) {
        int m = m0 + a_r0;
        const float* src = A + (long)(m < M ? m : 0) * lda + k0 + a_c0;
        cp_async16(sA[buf] + (a_r0*SM_STRIDE + a_c0)*4, src, m < M ? 16 : 0);
        m = m0 + a_r1;
        src = A + (long)(m < M ? m : 0) * lda + k0 + a_c1;
        cp_async16(sA[buf] + (a_r1*SM_STRIDE + a_c1)*4, src, m < M ? 16 : 0);
        const float* srcb = W + (long)(n0 + b_r) * K + k0 + b_c;
        cp_async16(sB[buf] + (b_r*SM_STRIDE + b_c)*4, srcb, 16);
        asm volatile("cp.async.commit_group;\n");
    };

    auto compute = [&](int buf) {
        const float* pa = As[buf];
        const float* pb = Bs[buf];
        #pragma unroll
        for (int ks = 0; ks < 2; ks++) {
            const int kk = ks * 8;
            unsigned a[2][4], b[4][2];
            #pragma unroll
            for (int mi = 0; mi < 2; mi++) {
                int r = wm*32 + mi*16 + grp;
                a[mi][0] = f2tf32(pa[(r    )*SM_STRIDE + kk + qd    ]);
                a[mi][1] = f2tf32(pa[(r + 8)*SM_STRIDE + kk + qd    ]);
                a[mi][2] = f2tf32(pa[(r    )*SM_STRIDE + kk + qd + 4]);
                a[mi][3] = f2tf32(pa[(r + 8)*SM_STRIDE + kk + qd + 4]);
            }
            #pragma unroll
            for (int ni = 0; ni < 4; ni++) {
                int n = wn*32 + ni*8 + grp;
                b[ni][0] = f2tf32(pb[n*SM_STRIDE + kk + qd    ]);
                b[ni][1] = f2tf32(pb[n*SM_STRIDE + kk + qd + 4]);
            }
            #pragma unroll
            for (int mi = 0; mi < 2; mi++)
                #pragma unroll
                for (int ni = 0; ni < 4; ni++)
                    mma_tf32(c[mi][ni], a[mi], b[ni][0], b[ni][1]);
        }
    };

    const int nt = K >> 4;
    load_tiles(0, 0);
    for (int t = 0; t < nt; t++) {
        const int buf = t & 1;
        if (t + 1 < nt) {
            load_tiles((t + 1) << 4, 1 - buf);
            asm volatile("cp.async.wait_group 1;\n");
        } else {
            asm volatile("cp.async.wait_group 0;\n");
        }
        __syncthreads();
        compute(buf);
        __syncthreads();
    }

    #pragma unroll
    for (int mi = 0; mi < 2; mi++) {
        #pragma unroll
        for (int ni = 0; ni < 4; ni++) {
            int col = n0 + wn*32 + ni*8 + 2*qd;
            float bsum0 = bias ? bias[col]     : 0.0f;
            float bsum1 = bias ? bias[col + 1] : 0.0f;
            #pragma unroll
            for (int rr = 0; rr < 2; rr++) {
                int row = m0 + wm*32 + mi*16 + grp + rr*8;
                if (row >= M) continue;
                float v0 = c[mi][ni][rr*2 + 0] + bsum0;
                float v1 = c[mi][ni][rr*2 + 1] + bsum1;
                if (DO_GELU) { v0 = gelu_exact(v0); v1 = gelu_exact(v1); }
                if (DO_RES) {
                    const float2 rv = *reinterpret_cast<const float2*>(&res[(long)row*ldo + col]);
                    v0 += rv.x; v1 += rv.y;
                }
                float2 ov; ov.x = v0; ov.y = v1;
                *reinterpret_cast<float2*>(&out[(long)row*ldo + col]) = ov;
            }
        }
    }
}

// ---------------- tensor-core flash attention ----------------
// block = (b, h, 64 queries), 256 threads = 8 warps.
// S = Q@K^T via mma (warp: 16x32); softmax in smem; O = P@V via mma (warp: 16x16).
#define ATQ 64
#define ATK 64
#define QKS 36   // Qs/Ks/Vs stride: (36*grp+qd)%32 = 4*grp+qd -> conflict-free
#define PSS 68   // Ps stride: 68%32=4 -> conflict-free fragment reads

__global__ void __launch_bounds__(256) attn_kernel(int adaptive) {
    __shared__ __align__(16) float Qs[ATQ*QKS];
    __shared__ __align__(16) float Ks[ATK*QKS];
    __shared__ __align__(16) float Vs[ATK*QKS];
    __shared__ __align__(16) float Ps[ATQ*PSS];
    __shared__ float m_s[ATQ], l_s[ATQ], corr_s[ATQ];

    const int tile = blockIdx.x;
    const int bh   = blockIdx.y;
    const int b = bh >> 3, h = bh & 7;
    const int t = threadIdx.x;
    const int q0 = tile * ATQ;
    const int warp = t >> 5, lane = t & 31;
    const int wm = warp >> 1, wn = warp & 1;       // 4 m-chunks x 2 n-halves
    const int grp = lane >> 2, qd = lane & 3;
    const int rv = t >> 2, sub = t & 3;            // row / quarter for loads+softmax
    const float scale = 0.1767766952966369f;       // 1/sqrt(32)

    // ---- load Q tile ----
    {
        int r = q0 + rv;
        float4 a0 = {0,0,0,0}, a1 = {0,0,0,0};
        if (r < TT) {
            const float4* src = reinterpret_cast<const float4*>(
                &g_qkv[((long)(b*TT + r))*QKVN + h*DHH + sub*8]);
            a0 = src[0]; a1 = src[1];
        }
        float4* qdst = reinterpret_cast<float4*>(&Qs[rv*QKS + sub*8]);
        qdst[0] = a0; qdst[1] = a1;
    }
    if (t < ATQ) { m_s[t] = -1e30f; l_s[t] = 0.0f; }
    __syncthreads();

    // ---- Q fragments (fixed for block): 4 ksteps ----
    unsigned aq[4][4];
    {
        int r0 = wm*16 + grp;
        #pragma unroll
        for (int ks = 0; ks < 4; ks++) {
            int kk = ks*8;
            aq[ks][0] = f2tf32(Qs[(r0    )*QKS + kk + qd    ]);
            aq[ks][1] = f2tf32(Qs[(r0 + 8)*QKS + kk + qd    ]);
            aq[ks][2] = f2tf32(Qs[(r0    )*QKS + kk + qd + 4]);
            aq[ks][3] = f2tf32(Qs[(r0 + 8)*QKS + kk + qd + 4]);
        }
    }

    float co[2][4] = {{0,0,0,0},{0,0,0,0}};   // O accum: warp m16 x n16

    for (int kt = 0; kt <= tile; kt++) {
        const int k0 = kt * ATK;
        __syncthreads();   // Ks/Vs/Ps of previous tile fully consumed

        // ---- load K, V tiles ----
        {
            int r = k0 + rv;
            float4 kv0 = {0,0,0,0}, kv1 = {0,0,0,0}, vv0 = {0,0,0,0}, vv1 = {0,0,0,0};
            if (r < TT) {
                const float4* ks = reinterpret_cast<const float4*>(
                    &g_qkv[((long)(b*TT + r))*QKVN + 256 + h*DHH + sub*8]);
                kv0 = ks[0]; kv1 = ks[1];
                const float4* vs = reinterpret_cast<const float4*>(
                    &g_qkv[((long)(b*TT + r))*QKVN + 512 + h*DHH + sub*8]);
                vv0 = vs[0]; vv1 = vs[1];
            }
            float4* kd = reinterpret_cast<float4*>(&Ks[rv*QKS + sub*8]);
            kd[0] = kv0; kd[1] = kv1;
            float4* vd = reinterpret_cast<float4*>(&Vs[rv*QKS + sub*8]);
            vd[0] = vv0; vd[1] = vv1;
        }
        __syncthreads();

        // ---- score mma: warp computes rows [wm*16, +16), cols [wn*32, +32) ----
        float cs[4][4];
        #pragma unroll
        for (int ni = 0; ni < 4; ni++)
            #pragma unroll
            for (int j = 0; j < 4; j++) cs[ni][j] = 0.0f;
        #pragma unroll
        for (int ks = 0; ks < 4; ks++) {
            int kk = ks*8;
            unsigned bf[4][2];
            #pragma unroll
            for (int ni = 0; ni < 4; ni++) {
                int kn = wn*32 + ni*8 + grp;
                bf[ni][0] = f2tf32(Ks[kn*QKS + kk + qd    ]);
                bf[ni][1] = f2tf32(Ks[kn*QKS + kk + qd + 4]);
            }
            #pragma unroll
            for (int ni = 0; ni < 4; ni++)
                mma_tf32(cs[ni], aq[ks], bf[ni][0], bf[ni][1]);
        }

        // ---- write S to Ps with scale + bias + causal mask ----
        const int r0 = wm*16 + grp;
        #pragma unroll
        for (int rr = 0; rr < 2; rr++) {
            int rl = r0 + rr*8;
            int q  = q0 + rl;
            bool qvalid = (q < TT);
            #pragma unroll
            for (int ni = 0; ni < 4; ni++) {
                int cl = wn*32 + ni*8 + 2*qd;
                int kc = k0 + cl;
                float v0, v1;
                if (kc > q || !qvalid) v0 = -1e30f;
                else {
                    float bias = adaptive ? g_h[((long)b*TT + q)*TT + kc] : 0.0f;
                    v0 = cs[ni][rr*2 + 0]*scale + bias;
                }
                if (kc + 1 > q || !qvalid) v1 = -1e30f;
                else {
                    float bias = adaptive ? g_h[((long)b*TT + q)*TT + kc + 1] : 0.0f;
                    v1 = cs[ni][rr*2 + 1]*scale + bias;
                }
                float2 sv; sv.x = v0; sv.y = v1;
                *reinterpret_cast<float2*>(&Ps[rl*PSS + cl]) = sv;
            }
        }
        __syncthreads();

        // ---- online softmax (4 threads per row) ----
        {
            float* pr = &Ps[rv*PSS + sub*16];
            float tmax = -1e30f;
            #pragma unroll
            for (int j = 0; j < 16; j++) tmax = fmaxf(tmax, pr[j]);
            tmax = fmaxf(tmax, __shfl_xor_sync(0xffffffffu, tmax, 1));
            tmax = fmaxf(tmax, __shfl_xor_sync(0xffffffffu, tmax, 2));
            float m_old = m_s[rv];
            float m_new = fmaxf(m_old, tmax);
            float tsum = 0.0f;
            #pragma unroll
            for (int j = 0; j < 16; j++) {
                float p = __expf(pr[j] - m_new);
                pr[j] = p;
                tsum += p;
            }
            tsum += __shfl_xor_sync(0xffffffffu, tsum, 1);
            tsum += __shfl_xor_sync(0xffffffffu, tsum, 2);
            if (sub == 0) {
                float corr = __expf(m_old - m_new);
                corr_s[rv] = corr;
                l_s[rv]    = l_s[rv]*corr + tsum;
                m_s[rv]    = m_new;
            }
        }
        __syncthreads();

        // ---- rescale O accum, then PV mma: warp rows [wm*16,+16), cols [wn*16,+16) ----
        {
            float c0f = corr_s[r0];
            float c1f = corr_s[r0 + 8];
            #pragma unroll
            for (int nj = 0; nj < 2; nj++) {
                co[nj][0] *= c0f; co[nj][1] *= c0f;
                co[nj][2] *= c1f; co[nj][3] *= c1f;
            }
            #pragma unroll
            for (int ks = 0; ks < 8; ks++) {
                int kk = ks*8;
                unsigned ap[4];
                ap[0] = f2tf32(Ps[(r0    )*PSS + kk + qd    ]);
                ap[1] = f2tf32(Ps[(r0 + 8)*PSS + kk + qd    ]);
                ap[2] = f2tf32(Ps[(r0    )*PSS + kk + qd + 4]);
                ap[3] = f2tf32(Ps[(r0 + 8)*PSS + kk + qd + 4]);
                #pragma unroll
                for (int nj = 0; nj < 2; nj++) {
                    int nc = wn*16 + nj*8 + grp;
                    unsigned b0 = f2tf32(Vs[(kk + qd    )*QKS + nc]);
                    unsigned b1 = f2tf32(Vs[(kk + qd + 4)*QKS + nc]);
                    mma_tf32(co[nj], ap, b0, b1);
                }
            }
        }
    }

    // ---- epilogue: normalize and write O ----
    {
        const int r0 = wm*16 + grp;
        int qa = q0 + r0, qb = q0 + r0 + 8;
        float inva = (qa < TT) ? 1.0f / l_s[r0]     : 0.0f;
        float invb = (qb < TT) ? 1.0f / l_s[r0 + 8] : 0.0f;
        #pragma unroll
        for (int nj = 0; nj < 2; nj++) {
            int col = wn*16 + nj*8 + 2*qd;
            if (qa < TT) {
                float2 ov; ov.x = co[nj][0]*inva; ov.y = co[nj][1]*inva;
                *reinterpret_cast<float2*>(&g_y[((long)(b*TT + qa))*CC + h*DHH + col]) = ov;
            }
            if (qb < TT) {
                float2 ov; ov.x = co[nj][2]*invb; ov.y = co[nj][3]*invb;
                *reinterpret_cast<float2*>(&g_y[((long)(b*TT + qb))*CC + h*DHH + col]) = ov;
            }
        }
    }
}

// ---------------- launch ----------------
extern "C" void kernel_launch(void* const* d_in, const int* in_sizes, int n_in,
                              void* d_out, int out_size) {
    const float* dc      = (const float*)d_in[0];
    const float* z       = (const float*)d_in[1];
    const float* p1      = (const float*)d_in[2];
    const float* p2      = (const float*)d_in[3];
    const float* p3      = (const float*)d_in[4];
    const float* frame   = (const float*)d_in[5];
    const float* cam     = (const float*)d_in[6];
    const float* timee   = (const float*)d_in[7];
    const float* locW1   = (const float*)d_in[8];
    const float* locb1   = (const float*)d_in[9];
    const float* locW2   = (const float*)d_in[10];
    const float* locb2   = (const float*)d_in[11];
    const float* ln1w    = (const float*)d_in[12];
    const float* ln1b    = (const float*)d_in[13];
    const float* Wq      = (const float*)d_in[14];
    const float* bq      = (const float*)d_in[15];
    const float* Wk      = (const float*)d_in[16];
    const float* bk      = (const float*)d_in[17];
    const float* Wv      = (const float*)d_in[18];
    const float* bv      = (const float*)d_in[19];
    const float* Wo      = (const float*)d_in[20];
    const float* bo      = (const float*)d_in[21];
    const float* ln2w    = (const float*)d_in[22];
    const float* ln2b    = (const float*)d_in[23];
    const float* W1      = (const float*)d_in[24];
    const float* b1      = (const float*)d_in[25];
    const float* W2      = (const float*)d_in[26];
    const float* b2      = (const float*)d_in[27];
    const float* lnfw    = (const float*)d_in[28];
    const float* lnfb    = (const float*)d_in[29];
    const float* headW   = (const float*)d_in[30];

    float *xp, *xnp, *qkvp, *yp, *ffnp, *wqkvp, *bqkvp;
    cudaGetSymbolAddress((void**)&xp,    g_x);
    cudaGetSymbolAddress((void**)&xnp,   g_xn);
    cudaGetSymbolAddress((void**)&qkvp,  g_qkv);
    cudaGetSymbolAddress((void**)&yp,    g_y);
    cudaGetSymbolAddress((void**)&ffnp,  g_ffn);
    cudaGetSymbolAddress((void**)&wqkvp, g_wqkv);
    cudaGetSymbolAddress((void**)&bqkvp, g_bqkv);

    const int MB = (MM + 127) / 128;     // 26
    dim3 g_qkvg(QKVN/64, MB);
    dim3 g_cc(CC/64, MB);
    dim3 g_ff(FF/64, MB);
    dim3 attn_grid((TT + ATQ - 1)/ATQ, BB*HH);   // (13, 32)

    {
        long np = (long)LL*QKVN*CC + (long)LL*QKVN;
        pack_qkv_kernel<<<(int)((np + 255) / 256), 256>>>(Wq, Wk, Wv, bq, bk, bv);
    }
    embed_kernel<<<(MM*CC + 255) / 256, 256>>>(dc, z, frame, cam, timee);

    for (int l = 0; l < LL; l++) {
        ln_kernel<<<MM, CC>>>(xp, ln1w + l*CC, ln1b + l*CC, xnp);

        gemm_tc<false,false><<<g_qkvg, 256>>>(xnp, CC, wqkvp + (long)l*QKVN*CC,
                                              bqkvp + l*QKVN, nullptr, qkvp, QKVN,
                                              MM, QKVN, CC);

        if (l == 0) {
            long nh = (long)BB*TT*TT;
            zero_h_kernel<<<(int)((nh + 255) / 256), 256>>>();
            loc1_kernel<<<3*BB, 64>>>(p1, p2, p3, locW1, locb1);
            loc2_kernel<<<(3*BB*65536 + 127) / 128, 128>>>(locW2, locb2);
        }

        attn_kernel<<<attn_grid, 256>>>((l % 2 == 0) ? 1 : 0);

        gemm_tc<false,true><<<g_cc, 256>>>(yp, CC, Wo + (long)l*CC*CC, bo + l*CC,
                                           xp, xp, CC, MM, CC, CC);

        ln_kernel<<<MM, CC>>>(xp, ln2w + l*CC, ln2b + l*CC, xnp);

        gemm_tc<true,false><<<g_ff, 256>>>(xnp, CC, W1 + (long)l*FF*CC, b1 + (long)l*FF,
                                           nullptr, ffnp, FF, MM, FF, CC);
        gemm_tc<false,true><<<g_cc, 256>>>(ffnp, FF, W2 + (long)l*CC*FF, b2 + l*CC,
                                           xp, xp, CC, MM, CC, FF);
    }

    ln_kernel<<<MM, CC>>>(xp, lnfw, lnfb, xnp);

    dim3 g_head(VOC/64, MB);
    gemm_tc<false,false><<<g_head, 256>>>(xnp, CC, headW, nullptr, nullptr,
                                          (float*)d_out, VOC, MM, VOC, CC);
}